// round 17
// baseline (speedup 1.0000x reference)
#include <cuda_runtime.h>
#include <cuda_fp16.h>
#include <cstdint>

#define BWIN 4096
#define NTOK 49
#define DIM  256
#define NH   8
#define HD   32
#define MTOT (BWIN * NTOK)            /* 200704 */
#define QKV_S (BWIN * NH * NTOK * HD) /* 51380224 */

typedef unsigned long long u64;
typedef unsigned int u32;

// ---------------- device scratch (allocation-free) ----------------
__device__ float g_v[QKV_S];                                // fp32 V [B][H][N][hd]
__device__ __align__(16) __half g_qh[QKV_S];                // fp16 Q
__device__ __align__(16) __half g_kh[QKV_S];                // fp16 K
__device__ float g_bias[NH * NTOK * NTOK];                  // [H][N][N]
__device__ __align__(16) __half g_xhi[(size_t)MTOT * DIM];
__device__ __align__(16) __half g_ahi[(size_t)MTOT * DIM];
__device__ __align__(16) __half g_alo[(size_t)MTOT * DIM];
__device__ __align__(16) __half g_wqhi[768 * 256];
__device__ __align__(16) __half g_wphi[256 * 256];

// ---------------- helpers ----------------
__device__ __forceinline__ u64 f2fma(u64 a, u64 b, u64 c) {
    u64 d;
    asm("fma.rn.f32x2 %0, %1, %2, %3;" : "=l"(d) : "l"(a), "l"(b), "l"(c));
    return d;
}
__device__ __forceinline__ void split_h(float x, unsigned short& h, unsigned short& l) {
    __half hb = __float2half_rn(x);
    float r = x - __half2float(hb);
    __half lb = __float2half_rn(r);
    h = __half_as_ushort(hb);
    l = __half_as_ushort(lb);
}
__device__ __forceinline__ u32 smem_u32(const void* p) {
    u32 a;
    asm("{ .reg .u64 t; cvta.to.shared.u64 t, %1; cvt.u32.u64 %0, t; }" : "=r"(a) : "l"(p));
    return a;
}

__device__ __forceinline__ void mma16816(float* d, u32 a0, u32 a1, u32 a2, u32 a3,
                                         u32 b0, u32 b1) {
    asm volatile(
        "mma.sync.aligned.m16n8k16.row.col.f32.f16.f16.f32 "
        "{%0,%1,%2,%3}, {%4,%5,%6,%7}, {%8,%9}, {%0,%1,%2,%3};"
        : "+f"(d[0]), "+f"(d[1]), "+f"(d[2]), "+f"(d[3])
        : "r"(a0), "r"(a1), "r"(a2), "r"(a3), "r"(b0), "r"(b1));
}

#define LDSM_X4(r0, r1, r2, r3, addr) \
    asm volatile("ldmatrix.sync.aligned.m8n8.x4.shared.b16 {%0,%1,%2,%3}, [%4];" \
        : "=r"(r0), "=r"(r1), "=r"(r2), "=r"(r3) : "r"(addr))

#define CP_ASYNC16(s, g) \
    asm volatile("cp.async.cg.shared.global [%0], [%1], 16;" :: "r"(s), "l"(g))
#define CP_COMMIT() asm volatile("cp.async.commit_group;" ::: "memory")
#define CP_WAITG(n) asm volatile("cp.async.wait_group %0;" :: "n"(n) : "memory")

// ---------------- fused preprocessing: conv_x(hi) + conv_w + bias gather ----------------
__global__ void pre_kernel(const float* __restrict__ x,
                           const float* __restrict__ wq,
                           const float* __restrict__ wp,
                           const float* __restrict__ table,
                           const int* __restrict__ rel) {
    const size_t idx = (size_t)blockIdx.x * 256 + threadIdx.x;

    if (idx < (size_t)MTOT * DIM / 4) {
        float4 v = ((const float4*)x)[idx];
        ((uint2*)g_xhi)[idx] = make_uint2(
            (u32)__half_as_ushort(__float2half_rn(v.x)) | ((u32)__half_as_ushort(__float2half_rn(v.y)) << 16),
            (u32)__half_as_ushort(__float2half_rn(v.z)) | ((u32)__half_as_ushort(__float2half_rn(v.w)) << 16));
    }
    const int nq4 = 768 * 256 / 4;
    const int np4 = 256 * 256 / 4;
    if (idx < (size_t)(nq4 + np4)) {
        if (idx < (size_t)nq4) {
            float4 v = ((const float4*)wq)[idx];
            ((uint2*)g_wqhi)[idx] = make_uint2(
                (u32)__half_as_ushort(__float2half_rn(v.x)) | ((u32)__half_as_ushort(__float2half_rn(v.y)) << 16),
                (u32)__half_as_ushort(__float2half_rn(v.z)) | ((u32)__half_as_ushort(__float2half_rn(v.w)) << 16));
        } else {
            int j = (int)idx - nq4;
            float4 v = ((const float4*)wp)[j];
            ((uint2*)g_wphi)[j] = make_uint2(
                (u32)__half_as_ushort(__float2half_rn(v.x)) | ((u32)__half_as_ushort(__float2half_rn(v.y)) << 16),
                (u32)__half_as_ushort(__float2half_rn(v.z)) | ((u32)__half_as_ushort(__float2half_rn(v.w)) << 16));
        }
    }
    if (idx < (size_t)(NH * NTOK * NTOK)) {
        int h = (int)idx / (NTOK * NTOK);
        int nm = (int)idx - h * (NTOK * NTOK);
        g_bias[idx] = table[rel[nm] * NH + h];
    }
}

// -------- tensor-core GEMM (512 threads, 32x32 warp tiles) --------
#define KC      32
#define RSTRIDE 40
#define TILE_E  (128 * RSTRIDE)
#define TILE_B  (TILE_E * 2)
#define NSTAGE  3

template <int MODE, int NTERMS>
__global__ __launch_bounds__(512)
void gemm_mma(const float* __restrict__ bias, float* __restrict__ out) {
    constexpr int STAGE_B = (NTERMS + 1) * TILE_B;
    extern __shared__ __half sm[];

    const __half* Ah = MODE ? g_ahi : g_xhi;
    const __half* Al = MODE ? g_alo : g_xhi;   // unused when NTERMS==1
    const __half* Bh = MODE ? g_wphi : g_wqhi;

    const int tid  = threadIdx.x;
    const int warp = tid >> 5;
    const int lane = tid & 31;
    const int g    = lane >> 2;
    const int t4   = lane & 3;
    const int wm   = warp >> 2;
    const int wn   = warp & 3;

    const int    o0 = blockIdx.x * 128;
    const size_t m0 = (size_t)blockIdx.y * 128;

    const u32 smem_base = smem_u32(sm);

    const int row = tid >> 2;
    const int seg = (tid & 3) * 8;

    const __half* gAh = Ah + (m0 + row) * 256 + seg;
    const __half* gAl = Al + (m0 + row) * 256 + seg;
    const __half* gBh = Bh + (size_t)(o0 + row) * 256 + seg;

    const u32 sb = (u32)(row * RSTRIDE + seg) * 2;

    const int q3 = (lane >> 3) & 1;
    const int q4 = (lane >> 4) & 1;
    const int r8 = lane & 7;
    const u32 offA  = 0 * TILE_B + (u32)(((wm * 32 + q3 * 8 + r8) * RSTRIDE) + q4 * 8) * 2;
    const u32 offB0 = NTERMS * TILE_B + (u32)(((wn * 32 + 0 * 16 + q4 * 8 + r8) * RSTRIDE) + q3 * 8) * 2;
    const u32 offB1 = NTERMS * TILE_B + (u32)(((wn * 32 + 1 * 16 + q4 * 8 + r8) * RSTRIDE) + q3 * 8) * 2;

    float acc[2][4][4];
#pragma unroll
    for (int a = 0; a < 2; ++a)
#pragma unroll
        for (int b = 0; b < 4; ++b)
#pragma unroll
            for (int c = 0; c < 4; ++c) acc[a][b][c] = 0.f;

#define ISSUE_STAGE(stg, kb) do {                                      \
        const u32 nx = smem_base + (u32)(stg) * STAGE_B;               \
        CP_ASYNC16(nx + 0 * TILE_B + sb, gAh + (kb));                  \
        if (NTERMS == 2) CP_ASYNC16(nx + 1 * TILE_B + sb, gAl + (kb)); \
        CP_ASYNC16(nx + NTERMS * TILE_B + sb, gBh + (kb));             \
        CP_COMMIT();                                                   \
    } while (0)

    ISSUE_STAGE(0, 0);
    ISSUE_STAGE(1, KC);

    int cur = 0;
#pragma unroll 1
    for (int kc = 0; kc < 8; ++kc) {
        if (kc < 7) CP_WAITG(1);
        else        CP_WAITG(0);
        __syncthreads();

        if (kc + 2 < 8) {
            int nxt = cur + 2; if (nxt >= 3) nxt -= 3;
            ISSUE_STAGE(nxt, (kc + 2) * KC);
        }

        const u32 stb = smem_base + (u32)cur * STAGE_B;
#pragma unroll
        for (int ks = 0; ks < 2; ++ks) {
            const u32 kso = (u32)(ks * 32);
            u32 bh[4][2];
            LDSM_X4(bh[0][0], bh[0][1], bh[1][0], bh[1][1], stb + offB0 + kso);
            LDSM_X4(bh[2][0], bh[2][1], bh[3][0], bh[3][1], stb + offB1 + kso);
#pragma unroll
            for (int mi = 0; mi < 2; ++mi) {
                const u32 ao = stb + offA + (u32)(mi * 16 * RSTRIDE * 2) + kso;
                u32 ah0, ah1, ah2, ah3;
                LDSM_X4(ah0, ah1, ah2, ah3, ao);
                u32 al0, al1, al2, al3;
                if (NTERMS == 2) LDSM_X4(al0, al1, al2, al3, ao + TILE_B);
#pragma unroll
                for (int ni = 0; ni < 4; ++ni) {
                    mma16816(acc[mi][ni], ah0, ah1, ah2, ah3, bh[ni][0], bh[ni][1]);
                    if (NTERMS == 2)
                        mma16816(acc[mi][ni], al0, al1, al2, al3, bh[ni][0], bh[ni][1]);
                }
            }
        }
        if (++cur == 3) cur = 0;
    }
#undef ISSUE_STAGE

    // ---- epilogue: bias add + store (q,k fp16; v fp32; proj fp32) ----
#pragma unroll
    for (int mi = 0; mi < 2; ++mi) {
        const int r0 = (int)m0 + wm * 32 + mi * 16 + g;
        const int r1 = r0 + 8;
#pragma unroll
        for (int ni = 0; ni < 4; ++ni) {
            const int c = o0 + wn * 32 + ni * 8 + 2 * t4;
            const float b0 = bias[c], b1 = bias[c + 1];
            float v00 = acc[mi][ni][0] + b0, v01 = acc[mi][ni][1] + b1;
            float v10 = acc[mi][ni][2] + b0, v11 = acc[mi][ni][3] + b1;
            if (MODE == 0) {
                const int which = c >> 8;           // 0=q,1=k,2=v
                const int head  = (c >> 5) & 7;
                const int d     = c & 31;
#pragma unroll
                for (int rr = 0; rr < 2; ++rr) {
                    const int m = rr ? r1 : r0;
                    const int bwin = m / NTOK;
                    const int n = m - bwin * NTOK;
                    const float y0 = rr ? v10 : v00;
                    const float y1 = rr ? v11 : v01;
                    const size_t idx = (((size_t)bwin * NH + head) * NTOK + n) * HD + d;
                    if (which == 2) {
                        *(float2*)(g_v + idx) = make_float2(y0, y1);
                    } else {
                        const u32 p = (u32)__half_as_ushort(__float2half_rn(y0)) |
                                      ((u32)__half_as_ushort(__float2half_rn(y1)) << 16);
                        *(u32*)((which ? g_kh : g_qh) + idx) = p;
                    }
                }
            } else {
                *(float2*)(out + (size_t)r0 * 256 + c) = make_float2(v00, v01);
                *(float2*)(out + (size_t)r1 * 256 + c) = make_float2(v10, v11);
            }
        }
    }
}

// ---------------- fused window attention (m-paired PV, transposed V) ----------------
// smem: sq/sk pool (s[49][52] aliases it), svT[32][60] (V transposed, cols 49..51 zero).
#define VPITCH 60

__global__ __launch_bounds__(64)
void attn_kernel() {
    __shared__ __align__(16) float pool[2][NTOK][34];   // sq, sk; s aliases
    __shared__ __align__(16) float svT[32][VPITCH];
    __shared__ float sinv[NTOK];
    float (*sq)[34] = pool[0];
    float (*sk)[34] = pool[1];
    float (*s)[52]  = (float (*)[52])&pool[0][0][0];    // 49*52=2548 <= 2*49*34=3332

    const int tid = threadIdx.x;
    const int bh = blockIdx.x;
    const int bwin = bh >> 3;
    const int h = bh & 7;

    // zero svT cols 49..51
    for (int i = tid; i < 96; i += 64) svT[i & 31][49 + (i >> 5)] = 0.f;

    const size_t base = (size_t)bh * (NTOK * HD);
    const uint4* q8 = (const uint4*)(g_qh + base);
    const uint4* k8 = (const uint4*)(g_kh + base);
    const float4* v4 = (const float4*)(g_v + base);

    // q,k: fp16 -> fp32 smem (196 uint4 each)
    for (int i = tid; i < 196; i += 64) {
        const int r = i >> 2, c8 = (i & 3) * 8;
        uint4 qv = q8[i];
        uint4 kv = k8[i];
        const __half2* qp = (const __half2*)&qv;
        const __half2* kp = (const __half2*)&kv;
#pragma unroll
        for (int j = 0; j < 4; ++j) {
            float2 f = __half22float2(qp[j]);
            sq[r][c8 + 2 * j] = f.x; sq[r][c8 + 2 * j + 1] = f.y;
            float2 e = __half22float2(kp[j]);
            sk[r][c8 + 2 * j] = e.x; sk[r][c8 + 2 * j + 1] = e.y;
        }
    }
    // v: fp32, transposed into svT[d][r]
    for (int i = tid; i < 392; i += 64) {
        const int r = i >> 3, c = (i & 7) * 4;
        float4 d = v4[i];
        svT[c][r] = d.x; svT[c + 1][r] = d.y; svT[c + 2][r] = d.z; svT[c + 3][r] = d.w;
    }
    __syncthreads();

    // QK^T into registers (reads sq/sk only)
    u64 acc[7][7];
    int n0 = 0, m0 = 0;
    if (tid < 49) {
        const int ti = tid / 7, tj = tid - ti * 7;
        n0 = ti * 7; m0 = tj * 7;
#pragma unroll
        for (int r = 0; r < 7; ++r)
#pragma unroll
            for (int cc = 0; cc < 7; ++cc) acc[r][cc] = 0ull;
#pragma unroll
        for (int kk = 0; kk < 16; ++kk) {
            u64 qv[7], kv[7];
#pragma unroll
            for (int r = 0; r < 7; ++r) qv[r] = *(const u64*)&sq[n0 + r][2 * kk];
#pragma unroll
            for (int cc = 0; cc < 7; ++cc) kv[cc] = *(const u64*)&sk[m0 + cc][2 * kk];
#pragma unroll
            for (int r = 0; r < 7; ++r)
#pragma unroll
                for (int cc = 0; cc < 7; ++cc) acc[r][cc] = f2fma(qv[r], kv[cc], acc[r][cc]);
        }
    }
    __syncthreads();   // sq/sk reads done before s (aliased) is written

    if (tid < 49) {
        const float scale = 0.17677669529663687f;
        const float* bb = g_bias + h * (NTOK * NTOK);
#pragma unroll
        for (int r = 0; r < 7; ++r)
#pragma unroll
            for (int cc = 0; cc < 7; ++cc) {
                const u64 a = acc[r][cc];
                const float lo = __uint_as_float((u32)(a & 0xffffffffull));
                const float hi = __uint_as_float((u32)(a >> 32));
                s[n0 + r][m0 + cc] = (lo + hi) * scale + bb[(n0 + r) * NTOK + m0 + cc];
            }
    }
    __syncthreads();

    // softmax: exp + sum; store UNSCALED e; zero pad cols 49..51; record 1/sum
    if (tid < 49) {
        float mx = -1e30f;
#pragma unroll
        for (int c = 0; c < NTOK; ++c) mx = fmaxf(mx, s[tid][c]);
        float sum = 0.f;
#pragma unroll
        for (int c = 0; c < NTOK; ++c) {
            float e = __expf(s[tid][c] - mx);
            s[tid][c] = e;
            sum += e;
        }
        s[tid][49] = 0.f; s[tid][50] = 0.f; s[tid][51] = 0.f;
        sinv[tid] = 1.f / sum;
    }
    __syncthreads();

    // P @ V: 56 threads, 7(n) x 4(d); paired over m (no dup movs)
    if (tid < 56) {
        const int ti = tid >> 3, tj = tid & 7;
        const int nn0 = ti * 7, d0 = tj * 4;
        u64 acc2[7][4];
#pragma unroll
        for (int r = 0; r < 7; ++r)
#pragma unroll
            for (int dd = 0; dd < 4; ++dd) acc2[r][dd] = 0ull;

#pragma unroll 1
        for (int mg = 0; mg < 13; ++mg) {
            const int m = mg * 4;
            u64 vp[4][2];
#pragma unroll
            for (int dd = 0; dd < 4; ++dd) {
                vp[dd][0] = *(const u64*)&svT[d0 + dd][m];
                vp[dd][1] = *(const u64*)&svT[d0 + dd][m + 2];
            }
#pragma unroll
            for (int r = 0; r < 7; ++r) {
                const u64 sp0 = *(const u64*)&s[nn0 + r][m];
                const u64 sp1 = *(const u64*)&s[nn0 + r][m + 2];
#pragma unroll
                for (int dd = 0; dd < 4; ++dd) {
                    acc2[r][dd] = f2fma(sp0, vp[dd][0], acc2[r][dd]);
                    acc2[r][dd] = f2fma(sp1, vp[dd][1], acc2[r][dd]);
                }
            }
        }

#pragma unroll
        for (int r = 0; r < 7; ++r) {
            const float inv = sinv[nn0 + r];
            unsigned short hh[4], ll[4];
#pragma unroll
            for (int dd = 0; dd < 4; ++dd) {
                const u64 a = acc2[r][dd];
                const float o = (__uint_as_float((u32)(a & 0xffffffffull)) +
                                 __uint_as_float((u32)(a >> 32))) * inv;
                split_h(o, hh[dd], ll[dd]);
            }
            uint2 vh = make_uint2((u32)hh[0] | ((u32)hh[1] << 16), (u32)hh[2] | ((u32)hh[3] << 16));
            uint2 vl = make_uint2((u32)ll[0] | ((u32)ll[1] << 16), (u32)ll[2] | ((u32)ll[3] << 16));
            const size_t off = ((size_t)bwin * NTOK + nn0 + r) * 256 + h * 32 + d0;
            *(uint2*)(g_ahi + off) = vh;
            *(uint2*)(g_alo + off) = vl;
        }
    }
}

// ---------------- launch ----------------
extern "C" void kernel_launch(void* const* d_in, const int* in_sizes, int n_in,
                              void* d_out, int out_size) {
    const float* x      = (const float*)d_in[0];
    const float* qkv_w  = (const float*)d_in[1];
    const float* qkv_b  = (const float*)d_in[2];
    const float* proj_w = (const float*)d_in[3];
    const float* proj_b = (const float*)d_in[4];
    const float* table  = (const float*)d_in[5];
    const int*   rel    = (const int*)d_in[6];
    float* out = (float*)d_out;

    const int SM1 = NSTAGE * 2 * TILE_B;   // 61440
    const int SM2 = NSTAGE * 3 * TILE_B;   // 92160

    static int smem_set = 0;
    if (!smem_set) {
        cudaFuncSetAttribute(gemm_mma<0, 1>, cudaFuncAttributeMaxDynamicSharedMemorySize, SM1);
        cudaFuncSetAttribute(gemm_mma<1, 2>, cudaFuncAttributeMaxDynamicSharedMemorySize, SM2);
        smem_set = 1;
    }

    pre_kernel<<<(int)(((size_t)MTOT * DIM / 4 + 255) / 256), 256>>>(x, qkv_w, proj_w, table, rel);
    gemm_mma<0, 1><<<dim3(6, MTOT / 128), 512, SM1>>>(qkv_b, nullptr);
    attn_kernel<<<BWIN * NH, 64>>>();
    gemm_mma<1, 2><<<dim3(2, MTOT / 128), 512, SM2>>>(proj_b, out);
}